// round 13
// baseline (speedup 1.0000x reference)
#include <cuda_runtime.h>
#include <cstdint>

// Problem constants
#define NQ   20
#define NL   8
#define BB   32
#define DIM  (1u << NQ)        // 1048576
#define NF4  (DIM / 4)         // 262144 float4s per statevector
#define TPB  256

// K2 geometry (measured best): 32 chunks x 16 batch-groups = 512 blocks
#define CHUNKS 32
#define BPG 2
#define NGRP (BB / BPG)                // 16
#define F4_PER_CHUNK (NF4 / CHUNKS)    // 8192
#define NIT 32                         // NIT*TPB == F4_PER_CHUNK

// Scratch
__device__ float g_G[DIM];
__device__ float g_part[CHUNKS * NGRP * BPG * 21];

// ---- packed f32x2 helpers ----
__device__ __forceinline__ uint64_t mulx2(uint64_t a, uint64_t b) {
    uint64_t r; asm("mul.rn.f32x2 %0,%1,%2;" : "=l"(r) : "l"(a), "l"(b)); return r;
}
__device__ __forceinline__ uint64_t addx2(uint64_t a, uint64_t b) {
    uint64_t r; asm("add.rn.f32x2 %0,%1,%2;" : "=l"(r) : "l"(a), "l"(b)); return r;
}
__device__ __forceinline__ uint64_t fmx2(uint64_t a, uint64_t b, uint64_t c) {
    uint64_t r; asm("fma.rn.f32x2 %0,%1,%2,%3;" : "=l"(r) : "l"(a), "l"(b), "l"(c)); return r;
}
__device__ __forceinline__ float lo32(uint64_t v) { return __uint_as_float((unsigned)v); }
__device__ __forceinline__ float hi32(uint64_t v) { return __uint_as_float((unsigned)(v >> 32)); }

union F4U2 { uint4 u; ulonglong2 l; };

// ---------------------------------------------------------------------------
// Kernel 1: G[i] = prod over 8 layers of noise[l,i]^2.
// SINGLE-WAVE geometry: 512 blocks x 256 thr x 2 float4/thread (perfectly
// balanced; 3.46 blocks/SM — no 136-block straggler wave as at 1024 blocks).
// Two independent product chains per thread for ILP.
// ---------------------------------------------------------------------------
__global__ void __launch_bounds__(TPB) k_prodG(const float* __restrict__ noise) {
    const unsigned i0 = blockIdx.x * (TPB * 2) + threadIdx.x;   // covers NF4 exactly
    const unsigned i1 = i0 + TPB;
    const float4* n4 = reinterpret_cast<const float4*>(noise);

    float4 va = __ldcs(n4 + i0);
    float4 vb = __ldcs(n4 + i1);
    float4 g0, g1;
    g0.x = va.x * va.x; g0.y = va.y * va.y; g0.z = va.z * va.z; g0.w = va.w * va.w;
    g1.x = vb.x * vb.x; g1.y = vb.y * vb.y; g1.z = vb.z * vb.z; g1.w = vb.w * vb.w;
#pragma unroll
    for (int l = 1; l < NL; l++) {
        va = __ldcs(n4 + (size_t)l * NF4 + i0);
        vb = __ldcs(n4 + (size_t)l * NF4 + i1);
        g0.x *= va.x * va.x; g0.y *= va.y * va.y; g0.z *= va.z * va.z; g0.w *= va.w * va.w;
        g1.x *= vb.x * vb.x; g1.y *= vb.y * vb.y; g1.z *= vb.z * vb.z; g1.w *= vb.w * vb.w;
    }
    reinterpret_cast<float4*>(g_G)[i0] = g0;
    reinterpret_cast<float4*>(g_G)[i1] = g1;
}

// ---------------------------------------------------------------------------
// Kernel 2: bit-masked reduction, packed f32x2 + radix-4 tree (measured best;
// DRAM-saturated — unchanged).
// ---------------------------------------------------------------------------
__global__ void __launch_bounds__(TPB, 4) k_bitsum(const float* __restrict__ amps) {
    const int bg    = blockIdx.x & (NGRP - 1);
    const int chunk = blockIdx.x >> 4;
    const int t     = threadIdx.x;

    const size_t sliceOff = (size_t)chunk * F4_PER_CHUNK + t;
    const ulonglong2* g4 = reinterpret_cast<const ulonglong2*>(g_G) + sliceOff;
    const uint4* a4_0 = reinterpret_cast<const uint4*>(amps)
                        + (size_t)(bg * BPG + 0) * NF4 + sliceOff;
    const uint4* a4_1 = reinterpret_cast<const uint4*>(amps)
                        + (size_t)(bg * BPG + 1) * NF4 + sliceOff;

    uint64_t T01[BPG] = {0, 0}, T23[BPG] = {0, 0};
    uint64_t J0[BPG] = {0, 0}, J1[BPG] = {0, 0}, J2[BPG] = {0, 0},
             J3[BPG] = {0, 0}, J4[BPG] = {0, 0};

#pragma unroll
    for (int j4 = 0; j4 < NIT / 4; j4++) {
        uint64_t sp[4][BPG];
#pragma unroll
        for (int jj = 0; jj < 4; jj++) {
            const int off = (j4 * 4 + jj) * TPB;
            ulonglong2 g = __ldg(g4 + off);               // L2-hot
            F4U2 A0, A1;
            A0.u = __ldcs(a4_0 + off);                    // streaming
            A1.u = __ldcs(a4_1 + off);
#pragma unroll
            for (int b2 = 0; b2 < BPG; b2++) {
                uint64_t a01 = b2 ? A1.l.x : A0.l.x;
                uint64_t a23 = b2 ? A1.l.y : A0.l.y;
                uint64_t t01 = mulx2(a01, a01);
                uint64_t t23 = mulx2(a23, a23);
                uint64_t w23 = mulx2(t23, g.y);
                sp[jj][b2]  = fmx2(t01, g.x, w23);        // (w0+w2, w1+w3)
                T01[b2] = fmx2(t01, g.x, T01[b2]);
                T23[b2] = addx2(T23[b2], w23);
            }
        }
#pragma unroll
        for (int b2 = 0; b2 < BPG; b2++) {
            J0[b2] = addx2(J0[b2], addx2(sp[1][b2], sp[3][b2]));   // qubit 10
            uint64_t P0 = addx2(sp[0][b2], sp[1][b2]);
            uint64_t P1 = addx2(sp[2][b2], sp[3][b2]);
            J1[b2] = addx2(J1[b2], P1);                            // qubit 11
            uint64_t Q = addx2(P0, P1);
            if (j4 & 1) J2[b2] = addx2(J2[b2], Q);                 // qubit 12
            if (j4 & 2) J3[b2] = addx2(J3[b2], Q);                 // qubit 13
            if (j4 & 4) J4[b2] = addx2(J4[b2], Q);                 // qubit 14
        }
    }

    __shared__ float sT[BPG][TPB];
    __shared__ float red[TPB / 32][BPG][7];
    const int wid = t >> 5, lane = t & 31;

#pragma unroll
    for (int b2 = 0; b2 < BPG; b2++) {
        float S0 = lo32(T01[b2]), S1 = hi32(T01[b2]);
        float S2 = lo32(T23[b2]), S3 = hi32(T23[b2]);
        float v[7];
        v[0] = S1 + S3;                                   // qubit 0
        v[1] = S2 + S3;                                   // qubit 1
        v[2] = lo32(J0[b2]) + hi32(J0[b2]);
        v[3] = lo32(J1[b2]) + hi32(J1[b2]);
        v[4] = lo32(J2[b2]) + hi32(J2[b2]);
        v[5] = lo32(J3[b2]) + hi32(J3[b2]);
        v[6] = lo32(J4[b2]) + hi32(J4[b2]);
        sT[b2][t] = (S0 + S1) + (S2 + S3);
#pragma unroll
        for (int k = 0; k < 7; k++) {
#pragma unroll
            for (int o = 16; o > 0; o >>= 1)
                v[k] += __shfl_xor_sync(0xffffffffu, v[k], o);
        }
        if (lane == 0) {
#pragma unroll
            for (int k = 0; k < 7; k++) red[wid][b2][k] = v[k];
        }
    }
    __syncthreads();

    if (wid < BPG) {
        const int b2 = wid;
        float v[8];
#pragma unroll
        for (int k = 0; k < 8; k++) v[k] = sT[b2][lane + 32 * k];
        float tt = ((v[0] + v[1]) + (v[2] + v[3])) + ((v[4] + v[5]) + (v[6] + v[7]));
        float m[8];
        m[5] = (v[1] + v[3]) + (v[5] + v[7]);             // qubit 7
        m[6] = (v[2] + v[3]) + (v[6] + v[7]);             // qubit 8
        m[7] = (v[4] + v[5]) + (v[6] + v[7]);             // qubit 9
#pragma unroll
        for (int k = 0; k < 5; k++)
            m[k] = ((lane >> k) & 1) ? tt : 0.f;          // qubits 2..6
#pragma unroll
        for (int o = 16; o > 0; o >>= 1) {
            tt += __shfl_xor_sync(0xffffffffu, tt, o);
#pragma unroll
            for (int k = 0; k < 8; k++)
                m[k] += __shfl_xor_sync(0xffffffffu, m[k], o);
        }
        if (lane == 0) {
            float q[21];
#pragma unroll
            for (int k = 0; k < 7; k++) {
                float s = 0.f;
#pragma unroll
                for (int w = 0; w < TPB / 32; w++) s += red[w][b2][k];
                q[(k < 2) ? k : (8 + k)] = s;             // q0,q1, q10..q14
            }
#pragma unroll
            for (int k = 0; k < 8; k++) q[2 + k] = m[k];  // qubits 2..9
#pragma unroll
            for (int k = 0; k < 5; k++)
                q[15 + k] = ((chunk >> k) & 1) ? tt : 0.f;
            q[20] = tt;
            float* dst = &g_part[(size_t)blockIdx.x * (BPG * 21) + b2 * 21];
#pragma unroll
            for (int k = 0; k < 21; k++) dst[k] = q[k];
        }
    }
}

// ---------------------------------------------------------------------------
// Kernel 3: one block per batch, 672 threads, smem tree + matvec.
// ---------------------------------------------------------------------------
__global__ void __launch_bounds__(672) k_final(const float* __restrict__ Wi,
                                               const float* __restrict__ bi,
                                               float* __restrict__ out) {
    const int b  = blockIdx.x;
    const int bg = b >> 1, b2 = b & 1;
    const int t  = threadIdx.x;
    const int c  = t / 21, k = t % 21;

    __shared__ float sm[CHUNKS * 21];
    sm[t] = __ldg(&g_part[(size_t)(c * NGRP + bg) * (BPG * 21) + b2 * 21 + k]);
    __syncthreads();

#pragma unroll
    for (int step = CHUNKS / 2; step >= 1; step >>= 1) {
        if (c < step) sm[c * 21 + k] += sm[(c + step) * 21 + k];
        __syncthreads();
    }

    if (t < NQ) {
        const float inv = 1.f / sm[20];
        float acc = bi[t];
#pragma unroll
        for (int q = 0; q < NQ; q++) acc += (sm[q] * inv) * Wi[q * NQ + t];
        out[b * NQ + t] = tanhf(acc);
    }
}

// ---------------------------------------------------------------------------
// Launch: 3 graph-capturable kernels, no syncs, no allocations.
// ---------------------------------------------------------------------------
extern "C" void kernel_launch(void* const* d_in, const int* in_sizes, int n_in,
                              void* d_out, int out_size) {
    int i_amps = 7, i_noise = 8, i_Wi = 9, i_bi = 10;
    for (int i = 0; i < n_in; i++) {
        const long sz = in_sizes[i];
        if (sz == (long)BB * (long)DIM)      i_amps  = i;
        else if (sz == (long)NL * (long)DIM) i_noise = i;
        else if (sz == NQ * NQ)              i_Wi    = i;
        else if (sz == NQ)                   i_bi    = i;
    }

    const float* noise = (const float*)d_in[i_noise];
    const float* amps  = (const float*)d_in[i_amps];
    const float* Wi    = (const float*)d_in[i_Wi];
    const float* bi    = (const float*)d_in[i_bi];
    float* out         = (float*)d_out;

    k_prodG <<<NF4 / (TPB * 2), TPB>>>(noise);  // 512 blocks, single wave
    k_bitsum<<<CHUNKS * NGRP, TPB>>>(amps);     // 512 blocks
    k_final <<<BB, 672>>>(Wi, bi, out);         //  32 blocks
}

// round 14
// speedup vs baseline: 1.1213x; 1.1213x over previous
#include <cuda_runtime.h>
#include <cstdint>

// Problem constants
#define NQ   20
#define NL   8
#define BB   32
#define DIM  (1u << NQ)        // 1048576
#define NF4  (DIM / 4)         // 262144 float4s per statevector
#define TPB  256

// K2 geometry (measured best): 32 chunks x 16 batch-groups = 512 blocks
#define CHUNKS 32
#define BPG 2
#define NGRP (BB / BPG)                // 16
#define F4_PER_CHUNK (NF4 / CHUNKS)    // 8192
#define NIT 32                         // NIT*TPB == F4_PER_CHUNK

// K1 geometry: 1024 blocks x 256 f4-slice, 8 layers x 4KB via cp.async.bulk
#define K1_SLICE 256                   // float4 per layer per block
#define K1_BYTES (K1_SLICE * 16)       // 4096 bytes per layer copy

// Scratch
__device__ float g_G[DIM];
__device__ float g_part[CHUNKS * NGRP * BPG * 21];

// ---- packed f32x2 helpers ----
__device__ __forceinline__ uint64_t mulx2(uint64_t a, uint64_t b) {
    uint64_t r; asm("mul.rn.f32x2 %0,%1,%2;" : "=l"(r) : "l"(a), "l"(b)); return r;
}
__device__ __forceinline__ uint64_t addx2(uint64_t a, uint64_t b) {
    uint64_t r; asm("add.rn.f32x2 %0,%1,%2;" : "=l"(r) : "l"(a), "l"(b)); return r;
}
__device__ __forceinline__ uint64_t fmx2(uint64_t a, uint64_t b, uint64_t c) {
    uint64_t r; asm("fma.rn.f32x2 %0,%1,%2,%3;" : "=l"(r) : "l"(a), "l"(b), "l"(c)); return r;
}
__device__ __forceinline__ float lo32(uint64_t v) { return __uint_as_float((unsigned)v); }
__device__ __forceinline__ float hi32(uint64_t v) { return __uint_as_float((unsigned)(v >> 32)); }

union F4U2 { uint4 u; ulonglong2 l; };

// ---------------------------------------------------------------------------
// Kernel 1: G[i] = prod over 8 layers of noise[l,i]^2 — TMA bulk-copy path.
// The TMA engine pipelines the 8 x 4KB copies chip-wide with no dependence on
// per-warp LDG MLP (which pinned every prior K1 variant at ~3.7 TB/s).
// ---------------------------------------------------------------------------
__global__ void __launch_bounds__(TPB) k_prodG(const float* __restrict__ noise) {
    __shared__ alignas(128) float4 buf[NL][K1_SLICE];   // 32 KB
    __shared__ alignas(8) uint64_t mbar;

    const int t = threadIdx.x;
    const size_t sliceF4 = (size_t)blockIdx.x * K1_SLICE;
    const float4* n4 = reinterpret_cast<const float4*>(noise);
    const uint32_t mbar_a = (uint32_t)__cvta_generic_to_shared(&mbar);

    if (t == 0) {
        asm volatile("mbarrier.init.shared.b64 [%0], 1;" :: "r"(mbar_a) : "memory");
    }
    __syncthreads();

    if (t == 0) {
        asm volatile("mbarrier.arrive.expect_tx.shared.b64 _, [%0], %1;"
                     :: "r"(mbar_a), "r"(NL * K1_BYTES) : "memory");
#pragma unroll
        for (int l = 0; l < NL; l++) {
            const uint32_t dst = (uint32_t)__cvta_generic_to_shared(&buf[l][0]);
            const float4* src = n4 + (size_t)l * NF4 + sliceF4;
            asm volatile(
                "cp.async.bulk.shared::cluster.global.mbarrier::complete_tx::bytes "
                "[%0], [%1], %2, [%3];"
                :: "r"(dst), "l"(src), "r"(K1_BYTES), "r"(mbar_a) : "memory");
        }
    }

    // all threads wait for the 32KB to land (acquire orders the smem reads)
    {
        uint32_t done;
        asm volatile(
            "{\n\t.reg .pred p;\n\t"
            "mbarrier.try_wait.parity.acquire.cta.shared::cta.b64 p, [%1], 0;\n\t"
            "selp.b32 %0, 1, 0, p;\n\t}"
            : "=r"(done) : "r"(mbar_a) : "memory");
        if (!done) {
            asm volatile(
                "{\n\t.reg .pred P1;\n\t"
                "WL_%=:\n\t"
                "mbarrier.try_wait.parity.acquire.cta.shared::cta.b64 P1, [%0], 0, 0x989680;\n\t"
                "@P1 bra.uni WD_%=;\n\t"
                "bra.uni WL_%=;\n\t"
                "WD_%=:\n\t}"
                :: "r"(mbar_a) : "memory");
        }
    }

    float4 v0 = buf[0][t], v1 = buf[1][t], v2 = buf[2][t], v3 = buf[3][t];
    float4 v4 = buf[4][t], v5 = buf[5][t], v6 = buf[6][t], v7 = buf[7][t];
    float4 g;
    g.x = ((v0.x*v0.x)*(v1.x*v1.x)) * ((v2.x*v2.x)*(v3.x*v3.x))
        * (((v4.x*v4.x)*(v5.x*v5.x)) * ((v6.x*v6.x)*(v7.x*v7.x)));
    g.y = ((v0.y*v0.y)*(v1.y*v1.y)) * ((v2.y*v2.y)*(v3.y*v3.y))
        * (((v4.y*v4.y)*(v5.y*v5.y)) * ((v6.y*v6.y)*(v7.y*v7.y)));
    g.z = ((v0.z*v0.z)*(v1.z*v1.z)) * ((v2.z*v2.z)*(v3.z*v3.z))
        * (((v4.z*v4.z)*(v5.z*v5.z)) * ((v6.z*v6.z)*(v7.z*v7.z)));
    g.w = ((v0.w*v0.w)*(v1.w*v1.w)) * ((v2.w*v2.w)*(v3.w*v3.w))
        * (((v4.w*v4.w)*(v5.w*v5.w)) * ((v6.w*v6.w)*(v7.w*v7.w)));
    reinterpret_cast<float4*>(g_G)[sliceF4 + t] = g;
}

// ---------------------------------------------------------------------------
// Kernel 2: bit-masked reduction, packed f32x2 + radix-4 tree (R12, best).
// ---------------------------------------------------------------------------
__global__ void __launch_bounds__(TPB, 4) k_bitsum(const float* __restrict__ amps) {
    const int bg    = blockIdx.x & (NGRP - 1);
    const int chunk = blockIdx.x >> 4;
    const int t     = threadIdx.x;

    const size_t sliceOff = (size_t)chunk * F4_PER_CHUNK + t;
    const ulonglong2* g4 = reinterpret_cast<const ulonglong2*>(g_G) + sliceOff;
    const uint4* a4_0 = reinterpret_cast<const uint4*>(amps)
                        + (size_t)(bg * BPG + 0) * NF4 + sliceOff;
    const uint4* a4_1 = reinterpret_cast<const uint4*>(amps)
                        + (size_t)(bg * BPG + 1) * NF4 + sliceOff;

    uint64_t T01[BPG] = {0, 0}, T23[BPG] = {0, 0};
    uint64_t J0[BPG] = {0, 0}, J1[BPG] = {0, 0}, J2[BPG] = {0, 0},
             J3[BPG] = {0, 0}, J4[BPG] = {0, 0};

#pragma unroll
    for (int j4 = 0; j4 < NIT / 4; j4++) {
        uint64_t sp[4][BPG];
#pragma unroll
        for (int jj = 0; jj < 4; jj++) {
            const int off = (j4 * 4 + jj) * TPB;
            ulonglong2 g = __ldg(g4 + off);               // L2-hot
            F4U2 A0, A1;
            A0.u = __ldcs(a4_0 + off);                    // streaming
            A1.u = __ldcs(a4_1 + off);
#pragma unroll
            for (int b2 = 0; b2 < BPG; b2++) {
                uint64_t a01 = b2 ? A1.l.x : A0.l.x;
                uint64_t a23 = b2 ? A1.l.y : A0.l.y;
                uint64_t t01 = mulx2(a01, a01);
                uint64_t t23 = mulx2(a23, a23);
                uint64_t w23 = mulx2(t23, g.y);
                sp[jj][b2]  = fmx2(t01, g.x, w23);        // (w0+w2, w1+w3)
                T01[b2] = fmx2(t01, g.x, T01[b2]);
                T23[b2] = addx2(T23[b2], w23);
            }
        }
#pragma unroll
        for (int b2 = 0; b2 < BPG; b2++) {
            J0[b2] = addx2(J0[b2], addx2(sp[1][b2], sp[3][b2]));   // qubit 10
            uint64_t P0 = addx2(sp[0][b2], sp[1][b2]);
            uint64_t P1 = addx2(sp[2][b2], sp[3][b2]);
            J1[b2] = addx2(J1[b2], P1);                            // qubit 11
            uint64_t Q = addx2(P0, P1);
            if (j4 & 1) J2[b2] = addx2(J2[b2], Q);                 // qubit 12
            if (j4 & 2) J3[b2] = addx2(J3[b2], Q);                 // qubit 13
            if (j4 & 4) J4[b2] = addx2(J4[b2], Q);                 // qubit 14
        }
    }

    __shared__ float sT[BPG][TPB];
    __shared__ float red[TPB / 32][BPG][7];
    const int wid = t >> 5, lane = t & 31;

#pragma unroll
    for (int b2 = 0; b2 < BPG; b2++) {
        float S0 = lo32(T01[b2]), S1 = hi32(T01[b2]);
        float S2 = lo32(T23[b2]), S3 = hi32(T23[b2]);
        float v[7];
        v[0] = S1 + S3;                                   // qubit 0
        v[1] = S2 + S3;                                   // qubit 1
        v[2] = lo32(J0[b2]) + hi32(J0[b2]);
        v[3] = lo32(J1[b2]) + hi32(J1[b2]);
        v[4] = lo32(J2[b2]) + hi32(J2[b2]);
        v[5] = lo32(J3[b2]) + hi32(J3[b2]);
        v[6] = lo32(J4[b2]) + hi32(J4[b2]);
        sT[b2][t] = (S0 + S1) + (S2 + S3);
#pragma unroll
        for (int k = 0; k < 7; k++) {
#pragma unroll
            for (int o = 16; o > 0; o >>= 1)
                v[k] += __shfl_xor_sync(0xffffffffu, v[k], o);
        }
        if (lane == 0) {
#pragma unroll
            for (int k = 0; k < 7; k++) red[wid][b2][k] = v[k];
        }
    }
    __syncthreads();

    if (wid < BPG) {
        const int b2 = wid;
        float v[8];
#pragma unroll
        for (int k = 0; k < 8; k++) v[k] = sT[b2][lane + 32 * k];
        float tt = ((v[0] + v[1]) + (v[2] + v[3])) + ((v[4] + v[5]) + (v[6] + v[7]));
        float m[8];
        m[5] = (v[1] + v[3]) + (v[5] + v[7]);             // qubit 7
        m[6] = (v[2] + v[3]) + (v[6] + v[7]);             // qubit 8
        m[7] = (v[4] + v[5]) + (v[6] + v[7]);             // qubit 9
#pragma unroll
        for (int k = 0; k < 5; k++)
            m[k] = ((lane >> k) & 1) ? tt : 0.f;          // qubits 2..6
#pragma unroll
        for (int o = 16; o > 0; o >>= 1) {
            tt += __shfl_xor_sync(0xffffffffu, tt, o);
#pragma unroll
            for (int k = 0; k < 8; k++)
                m[k] += __shfl_xor_sync(0xffffffffu, m[k], o);
        }
        if (lane == 0) {
            float q[21];
#pragma unroll
            for (int k = 0; k < 7; k++) {
                float s = 0.f;
#pragma unroll
                for (int w = 0; w < TPB / 32; w++) s += red[w][b2][k];
                q[(k < 2) ? k : (8 + k)] = s;             // q0,q1, q10..q14
            }
#pragma unroll
            for (int k = 0; k < 8; k++) q[2 + k] = m[k];  // qubits 2..9
#pragma unroll
            for (int k = 0; k < 5; k++)
                q[15 + k] = ((chunk >> k) & 1) ? tt : 0.f;
            q[20] = tt;
            float* dst = &g_part[(size_t)blockIdx.x * (BPG * 21) + b2 * 21];
#pragma unroll
            for (int k = 0; k < 21; k++) dst[k] = q[k];
        }
    }
}

// ---------------------------------------------------------------------------
// Kernel 3: one block per batch, 672 threads, smem tree + matvec (R12).
// ---------------------------------------------------------------------------
__global__ void __launch_bounds__(672) k_final(const float* __restrict__ Wi,
                                               const float* __restrict__ bi,
                                               float* __restrict__ out) {
    const int b  = blockIdx.x;
    const int bg = b >> 1, b2 = b & 1;
    const int t  = threadIdx.x;
    const int c  = t / 21, k = t % 21;

    __shared__ float sm[CHUNKS * 21];
    sm[t] = __ldg(&g_part[(size_t)(c * NGRP + bg) * (BPG * 21) + b2 * 21 + k]);
    __syncthreads();

#pragma unroll
    for (int step = CHUNKS / 2; step >= 1; step >>= 1) {
        if (c < step) sm[c * 21 + k] += sm[(c + step) * 21 + k];
        __syncthreads();
    }

    if (t < NQ) {
        const float inv = 1.f / sm[20];
        float acc = bi[t];
#pragma unroll
        for (int q = 0; q < NQ; q++) acc += (sm[q] * inv) * Wi[q * NQ + t];
        out[b * NQ + t] = tanhf(acc);
    }
}

// ---------------------------------------------------------------------------
// Launch: 3 graph-capturable kernels, no syncs, no allocations.
// ---------------------------------------------------------------------------
extern "C" void kernel_launch(void* const* d_in, const int* in_sizes, int n_in,
                              void* d_out, int out_size) {
    int i_amps = 7, i_noise = 8, i_Wi = 9, i_bi = 10;
    for (int i = 0; i < n_in; i++) {
        const long sz = in_sizes[i];
        if (sz == (long)BB * (long)DIM)      i_amps  = i;
        else if (sz == (long)NL * (long)DIM) i_noise = i;
        else if (sz == NQ * NQ)              i_Wi    = i;
        else if (sz == NQ)                   i_bi    = i;
    }

    const float* noise = (const float*)d_in[i_noise];
    const float* amps  = (const float*)d_in[i_amps];
    const float* Wi    = (const float*)d_in[i_Wi];
    const float* bi    = (const float*)d_in[i_bi];
    float* out         = (float*)d_out;

    k_prodG <<<NF4 / K1_SLICE, TPB>>>(noise);   // 1024 blocks, TMA bulk copies
    k_bitsum<<<CHUNKS * NGRP, TPB>>>(amps);     //  512 blocks (R12, best)
    k_final <<<BB, 672>>>(Wi, bi, out);         //   32 blocks (R12)
}

// round 15
// speedup vs baseline: 1.1936x; 1.0645x over previous
#include <cuda_runtime.h>
#include <cstdint>

// Problem constants
#define NQ   20
#define NL   8
#define BB   32
#define DIM  (1u << NQ)        // 1048576
#define NF4  (DIM / 4)         // 262144 float4s per statevector
#define TPB  256

// K2 geometry (measured best): 32 chunks x 16 batch-groups = 512 blocks
#define CHUNKS 32
#define BPG 2
#define NGRP (BB / BPG)                // 16
#define F4_PER_CHUNK (NF4 / CHUNKS)    // 8192
#define NIT 32                         // NIT*TPB == F4_PER_CHUNK

// Scratch: G stored as bf16 (uint2 = 4 values), halves its L2 re-read traffic
__device__ uint2 g_Gh[NF4];
__device__ float g_part[CHUNKS * NGRP * BPG * 21];

// ---- packed f32x2 helpers ----
__device__ __forceinline__ uint64_t mulx2(uint64_t a, uint64_t b) {
    uint64_t r; asm("mul.rn.f32x2 %0,%1,%2;" : "=l"(r) : "l"(a), "l"(b)); return r;
}
__device__ __forceinline__ uint64_t addx2(uint64_t a, uint64_t b) {
    uint64_t r; asm("add.rn.f32x2 %0,%1,%2;" : "=l"(r) : "l"(a), "l"(b)); return r;
}
__device__ __forceinline__ uint64_t fmx2(uint64_t a, uint64_t b, uint64_t c) {
    uint64_t r; asm("fma.rn.f32x2 %0,%1,%2,%3;" : "=l"(r) : "l"(a), "l"(b), "l"(c)); return r;
}
__device__ __forceinline__ float lo32(uint64_t v) { return __uint_as_float((unsigned)v); }
__device__ __forceinline__ float hi32(uint64_t v) { return __uint_as_float((unsigned)(v >> 32)); }

// expand 2 packed bf16 -> packed f32x2 (2 PRMT on the ALU pipe, fma pipe untouched)
__device__ __forceinline__ uint64_t bf2_to_f32x2(uint32_t p) {
    uint32_t lo, hi;
    asm("prmt.b32 %0, %1, 0, 0x1044;" : "=r"(lo) : "r"(p));   // {0,0,b0,b1} = bf16lo<<16
    asm("prmt.b32 %0, %1, 0, 0x3244;" : "=r"(hi) : "r"(p));   // {0,0,b2,b3} = bf16hi<<16
    uint64_t r; asm("mov.b64 %0, {%1,%2};" : "=l"(r) : "r"(lo), "r"(hi));
    return r;
}

union F4U2 { uint4 u; ulonglong2 l; };

// ---------------------------------------------------------------------------
// Kernel 1: G[i] = prod over 8 layers of noise[l,i]^2, stored as bf16.
// Simple rolling-product version (every fancier variant measured identical).
// ---------------------------------------------------------------------------
__global__ void __launch_bounds__(TPB) k_prodG(const float* __restrict__ noise) {
    unsigned i = blockIdx.x * TPB + threadIdx.x;
    const float4* n4 = reinterpret_cast<const float4*>(noise);
    float4 v = n4[i];
    float4 g;
    g.x = v.x * v.x; g.y = v.y * v.y; g.z = v.z * v.z; g.w = v.w * v.w;
#pragma unroll
    for (int l = 1; l < NL; l++) {
        v = n4[(size_t)l * NF4 + i];
        g.x *= v.x * v.x; g.y *= v.y * v.y; g.z *= v.z * v.z; g.w *= v.w * v.w;
    }
    uint2 p;
    asm("cvt.rn.bf16x2.f32 %0, %1, %2;" : "=r"(p.x) : "f"(g.y), "f"(g.x));
    asm("cvt.rn.bf16x2.f32 %0, %1, %2;" : "=r"(p.y) : "f"(g.w), "f"(g.z));
    g_Gh[i] = p;
}

// ---------------------------------------------------------------------------
// Kernel 2: bit-masked reduction, packed f32x2 + radix-4 tree; G read as bf16
// (L2 traffic for G halved: 64 -> 32 MB; K2 is LTS-cap-bound).
// ---------------------------------------------------------------------------
__global__ void __launch_bounds__(TPB, 4) k_bitsum(const float* __restrict__ amps) {
    const int bg    = blockIdx.x & (NGRP - 1);
    const int chunk = blockIdx.x >> 4;
    const int t     = threadIdx.x;

    const size_t sliceOff = (size_t)chunk * F4_PER_CHUNK + t;
    const uint2* g2   = g_Gh + sliceOff;
    const uint4* a4_0 = reinterpret_cast<const uint4*>(amps)
                        + (size_t)(bg * BPG + 0) * NF4 + sliceOff;
    const uint4* a4_1 = reinterpret_cast<const uint4*>(amps)
                        + (size_t)(bg * BPG + 1) * NF4 + sliceOff;

    uint64_t T01[BPG] = {0, 0}, T23[BPG] = {0, 0};
    uint64_t J0[BPG] = {0, 0}, J1[BPG] = {0, 0}, J2[BPG] = {0, 0},
             J3[BPG] = {0, 0}, J4[BPG] = {0, 0};

#pragma unroll
    for (int j4 = 0; j4 < NIT / 4; j4++) {
        uint64_t sp[4][BPG];
#pragma unroll
        for (int jj = 0; jj < 4; jj++) {
            const int off = (j4 * 4 + jj) * TPB;
            uint2 gh = __ldg(g2 + off);                   // 8B, L2-hot
            uint64_t gx01 = bf2_to_f32x2(gh.x);           // (G0,G1) packed f32x2
            uint64_t gx23 = bf2_to_f32x2(gh.y);           // (G2,G3)
            F4U2 A0, A1;
            A0.u = __ldcs(a4_0 + off);                    // streaming
            A1.u = __ldcs(a4_1 + off);
#pragma unroll
            for (int b2 = 0; b2 < BPG; b2++) {
                uint64_t a01 = b2 ? A1.l.x : A0.l.x;
                uint64_t a23 = b2 ? A1.l.y : A0.l.y;
                uint64_t t01 = mulx2(a01, a01);
                uint64_t t23 = mulx2(a23, a23);
                uint64_t w23 = mulx2(t23, gx23);
                sp[jj][b2]  = fmx2(t01, gx01, w23);       // (w0+w2, w1+w3)
                T01[b2] = fmx2(t01, gx01, T01[b2]);
                T23[b2] = addx2(T23[b2], w23);
            }
        }
#pragma unroll
        for (int b2 = 0; b2 < BPG; b2++) {
            J0[b2] = addx2(J0[b2], addx2(sp[1][b2], sp[3][b2]));   // qubit 10
            uint64_t P0 = addx2(sp[0][b2], sp[1][b2]);
            uint64_t P1 = addx2(sp[2][b2], sp[3][b2]);
            J1[b2] = addx2(J1[b2], P1);                            // qubit 11
            uint64_t Q = addx2(P0, P1);
            if (j4 & 1) J2[b2] = addx2(J2[b2], Q);                 // qubit 12
            if (j4 & 2) J3[b2] = addx2(J3[b2], Q);                 // qubit 13
            if (j4 & 4) J4[b2] = addx2(J4[b2], Q);                 // qubit 14
        }
    }

    __shared__ float sT[BPG][TPB];
    __shared__ float red[TPB / 32][BPG][7];
    const int wid = t >> 5, lane = t & 31;

#pragma unroll
    for (int b2 = 0; b2 < BPG; b2++) {
        float S0 = lo32(T01[b2]), S1 = hi32(T01[b2]);
        float S2 = lo32(T23[b2]), S3 = hi32(T23[b2]);
        float v[7];
        v[0] = S1 + S3;                                   // qubit 0
        v[1] = S2 + S3;                                   // qubit 1
        v[2] = lo32(J0[b2]) + hi32(J0[b2]);
        v[3] = lo32(J1[b2]) + hi32(J1[b2]);
        v[4] = lo32(J2[b2]) + hi32(J2[b2]);
        v[5] = lo32(J3[b2]) + hi32(J3[b2]);
        v[6] = lo32(J4[b2]) + hi32(J4[b2]);
        sT[b2][t] = (S0 + S1) + (S2 + S3);
#pragma unroll
        for (int k = 0; k < 7; k++) {
#pragma unroll
            for (int o = 16; o > 0; o >>= 1)
                v[k] += __shfl_xor_sync(0xffffffffu, v[k], o);
        }
        if (lane == 0) {
#pragma unroll
            for (int k = 0; k < 7; k++) red[wid][b2][k] = v[k];
        }
    }
    __syncthreads();

    if (wid < BPG) {
        const int b2 = wid;
        float v[8];
#pragma unroll
        for (int k = 0; k < 8; k++) v[k] = sT[b2][lane + 32 * k];
        float tt = ((v[0] + v[1]) + (v[2] + v[3])) + ((v[4] + v[5]) + (v[6] + v[7]));
        float m[8];
        m[5] = (v[1] + v[3]) + (v[5] + v[7]);             // qubit 7
        m[6] = (v[2] + v[3]) + (v[6] + v[7]);             // qubit 8
        m[7] = (v[4] + v[5]) + (v[6] + v[7]);             // qubit 9
#pragma unroll
        for (int k = 0; k < 5; k++)
            m[k] = ((lane >> k) & 1) ? tt : 0.f;          // qubits 2..6
#pragma unroll
        for (int o = 16; o > 0; o >>= 1) {
            tt += __shfl_xor_sync(0xffffffffu, tt, o);
#pragma unroll
            for (int k = 0; k < 8; k++)
                m[k] += __shfl_xor_sync(0xffffffffu, m[k], o);
        }
        if (lane == 0) {
            float q[21];
#pragma unroll
            for (int k = 0; k < 7; k++) {
                float s = 0.f;
#pragma unroll
                for (int w = 0; w < TPB / 32; w++) s += red[w][b2][k];
                q[(k < 2) ? k : (8 + k)] = s;             // q0,q1, q10..q14
            }
#pragma unroll
            for (int k = 0; k < 8; k++) q[2 + k] = m[k];  // qubits 2..9
#pragma unroll
            for (int k = 0; k < 5; k++)
                q[15 + k] = ((chunk >> k) & 1) ? tt : 0.f;
            q[20] = tt;
            float* dst = &g_part[(size_t)blockIdx.x * (BPG * 21) + b2 * 21];
#pragma unroll
            for (int k = 0; k < 21; k++) dst[k] = q[k];
        }
    }
}

// ---------------------------------------------------------------------------
// Kernel 3: one block per batch, 672 threads, smem tree + matvec.
// ---------------------------------------------------------------------------
__global__ void __launch_bounds__(672) k_final(const float* __restrict__ Wi,
                                               const float* __restrict__ bi,
                                               float* __restrict__ out) {
    const int b  = blockIdx.x;
    const int bg = b >> 1, b2 = b & 1;
    const int t  = threadIdx.x;
    const int c  = t / 21, k = t % 21;

    __shared__ float sm[CHUNKS * 21];
    sm[t] = __ldg(&g_part[(size_t)(c * NGRP + bg) * (BPG * 21) + b2 * 21 + k]);
    __syncthreads();

#pragma unroll
    for (int step = CHUNKS / 2; step >= 1; step >>= 1) {
        if (c < step) sm[c * 21 + k] += sm[(c + step) * 21 + k];
        __syncthreads();
    }

    if (t < NQ) {
        const float inv = 1.f / sm[20];
        float acc = bi[t];
#pragma unroll
        for (int q = 0; q < NQ; q++) acc += (sm[q] * inv) * Wi[q * NQ + t];
        out[b * NQ + t] = tanhf(acc);
    }
}

// ---------------------------------------------------------------------------
// Launch: 3 graph-capturable kernels, no syncs, no allocations.
// ---------------------------------------------------------------------------
extern "C" void kernel_launch(void* const* d_in, const int* in_sizes, int n_in,
                              void* d_out, int out_size) {
    int i_amps = 7, i_noise = 8, i_Wi = 9, i_bi = 10;
    for (int i = 0; i < n_in; i++) {
        const long sz = in_sizes[i];
        if (sz == (long)BB * (long)DIM)      i_amps  = i;
        else if (sz == (long)NL * (long)DIM) i_noise = i;
        else if (sz == NQ * NQ)              i_Wi    = i;
        else if (sz == NQ)                   i_bi    = i;
    }

    const float* noise = (const float*)d_in[i_noise];
    const float* amps  = (const float*)d_in[i_amps];
    const float* Wi    = (const float*)d_in[i_Wi];
    const float* bi    = (const float*)d_in[i_bi];
    float* out         = (float*)d_out;

    k_prodG <<<NF4 / TPB, TPB>>>(noise);        // 1024 blocks, bf16 G out
    k_bitsum<<<CHUNKS * NGRP, TPB>>>(amps);     //  512 blocks, bf16 G in
    k_final <<<BB, 672>>>(Wi, bi, out);         //   32 blocks
}

// round 16
// speedup vs baseline: 1.1949x; 1.0010x over previous
#include <cuda_runtime.h>
#include <cstdint>

// Problem constants
#define NQ   20
#define NL   8
#define BB   32
#define DIM  (1u << NQ)        // 1048576
#define NF4  (DIM / 4)         // 262144 float4s per statevector
#define TPB  256

// K1 geometry: 512 blocks x 512 threads, 1 float4/thread.
// Single wave (occ cap 4 blocks/SM -> 592 slots >= 512) AND ~55 warps/SM.
#define TPB1 512

// K2 geometry (measured best): 32 chunks x 16 batch-groups = 512 blocks
#define CHUNKS 32
#define BPG 2
#define NGRP (BB / BPG)                // 16
#define F4_PER_CHUNK (NF4 / CHUNKS)    // 8192
#define NIT 32                         // NIT*TPB == F4_PER_CHUNK

// Scratch: G stored as bf16 (uint2 = 4 values) — halves its L2 re-read traffic
__device__ uint2 g_Gh[NF4];
__device__ float g_part[CHUNKS * NGRP * BPG * 21];

// ---- packed f32x2 helpers ----
__device__ __forceinline__ uint64_t mulx2(uint64_t a, uint64_t b) {
    uint64_t r; asm("mul.rn.f32x2 %0,%1,%2;" : "=l"(r) : "l"(a), "l"(b)); return r;
}
__device__ __forceinline__ uint64_t addx2(uint64_t a, uint64_t b) {
    uint64_t r; asm("add.rn.f32x2 %0,%1,%2;" : "=l"(r) : "l"(a), "l"(b)); return r;
}
__device__ __forceinline__ uint64_t fmx2(uint64_t a, uint64_t b, uint64_t c) {
    uint64_t r; asm("fma.rn.f32x2 %0,%1,%2,%3;" : "=l"(r) : "l"(a), "l"(b), "l"(c)); return r;
}
__device__ __forceinline__ float lo32(uint64_t v) { return __uint_as_float((unsigned)v); }
__device__ __forceinline__ float hi32(uint64_t v) { return __uint_as_float((unsigned)(v >> 32)); }

// expand 2 packed bf16 -> packed f32x2 (2 PRMT on the ALU pipe)
__device__ __forceinline__ uint64_t bf2_to_f32x2(uint32_t p) {
    uint32_t lo, hi;
    asm("prmt.b32 %0, %1, 0, 0x1044;" : "=r"(lo) : "r"(p));
    asm("prmt.b32 %0, %1, 0, 0x3244;" : "=r"(hi) : "r"(p));
    uint64_t r; asm("mov.b64 %0, {%1,%2};" : "=l"(r) : "r"(lo), "r"(hi));
    return r;
}

union F4U2 { uint4 u; ulonglong2 l; };

// ---------------------------------------------------------------------------
// Kernel 1: G[i] = prod over 8 layers of noise[l,i]^2, stored as bf16.
// 512 blocks x 512 threads: single wave at ~55 warps/SM.
// ---------------------------------------------------------------------------
__global__ void __launch_bounds__(TPB1) k_prodG(const float* __restrict__ noise) {
    unsigned i = blockIdx.x * TPB1 + threadIdx.x;       // covers NF4 exactly
    const float4* n4 = reinterpret_cast<const float4*>(noise);
    float4 v = n4[i];
    float4 g;
    g.x = v.x * v.x; g.y = v.y * v.y; g.z = v.z * v.z; g.w = v.w * v.w;
#pragma unroll
    for (int l = 1; l < NL; l++) {
        v = n4[(size_t)l * NF4 + i];
        g.x *= v.x * v.x; g.y *= v.y * v.y; g.z *= v.z * v.z; g.w *= v.w * v.w;
    }
    uint2 p;
    asm("cvt.rn.bf16x2.f32 %0, %1, %2;" : "=r"(p.x) : "f"(g.y), "f"(g.x));
    asm("cvt.rn.bf16x2.f32 %0, %1, %2;" : "=r"(p.y) : "f"(g.w), "f"(g.z));
    g_Gh[i] = p;
}

// ---------------------------------------------------------------------------
// Kernel 2: bit-masked reduction, packed f32x2 + radix-4 tree; G read as bf16
// (R15 version — best measured; DO NOT TOUCH).
// ---------------------------------------------------------------------------
__global__ void __launch_bounds__(TPB, 4) k_bitsum(const float* __restrict__ amps) {
    const int bg    = blockIdx.x & (NGRP - 1);
    const int chunk = blockIdx.x >> 4;
    const int t     = threadIdx.x;

    const size_t sliceOff = (size_t)chunk * F4_PER_CHUNK + t;
    const uint2* g2   = g_Gh + sliceOff;
    const uint4* a4_0 = reinterpret_cast<const uint4*>(amps)
                        + (size_t)(bg * BPG + 0) * NF4 + sliceOff;
    const uint4* a4_1 = reinterpret_cast<const uint4*>(amps)
                        + (size_t)(bg * BPG + 1) * NF4 + sliceOff;

    uint64_t T01[BPG] = {0, 0}, T23[BPG] = {0, 0};
    uint64_t J0[BPG] = {0, 0}, J1[BPG] = {0, 0}, J2[BPG] = {0, 0},
             J3[BPG] = {0, 0}, J4[BPG] = {0, 0};

#pragma unroll
    for (int j4 = 0; j4 < NIT / 4; j4++) {
        uint64_t sp[4][BPG];
#pragma unroll
        for (int jj = 0; jj < 4; jj++) {
            const int off = (j4 * 4 + jj) * TPB;
            uint2 gh = __ldg(g2 + off);                   // 8B, L2-hot
            uint64_t gx01 = bf2_to_f32x2(gh.x);
            uint64_t gx23 = bf2_to_f32x2(gh.y);
            F4U2 A0, A1;
            A0.u = __ldcs(a4_0 + off);                    // streaming
            A1.u = __ldcs(a4_1 + off);
#pragma unroll
            for (int b2 = 0; b2 < BPG; b2++) {
                uint64_t a01 = b2 ? A1.l.x : A0.l.x;
                uint64_t a23 = b2 ? A1.l.y : A0.l.y;
                uint64_t t01 = mulx2(a01, a01);
                uint64_t t23 = mulx2(a23, a23);
                uint64_t w23 = mulx2(t23, gx23);
                sp[jj][b2]  = fmx2(t01, gx01, w23);       // (w0+w2, w1+w3)
                T01[b2] = fmx2(t01, gx01, T01[b2]);
                T23[b2] = addx2(T23[b2], w23);
            }
        }
#pragma unroll
        for (int b2 = 0; b2 < BPG; b2++) {
            J0[b2] = addx2(J0[b2], addx2(sp[1][b2], sp[3][b2]));   // qubit 10
            uint64_t P0 = addx2(sp[0][b2], sp[1][b2]);
            uint64_t P1 = addx2(sp[2][b2], sp[3][b2]);
            J1[b2] = addx2(J1[b2], P1);                            // qubit 11
            uint64_t Q = addx2(P0, P1);
            if (j4 & 1) J2[b2] = addx2(J2[b2], Q);                 // qubit 12
            if (j4 & 2) J3[b2] = addx2(J3[b2], Q);                 // qubit 13
            if (j4 & 4) J4[b2] = addx2(J4[b2], Q);                 // qubit 14
        }
    }

    __shared__ float sT[BPG][TPB];
    __shared__ float red[TPB / 32][BPG][7];
    const int wid = t >> 5, lane = t & 31;

#pragma unroll
    for (int b2 = 0; b2 < BPG; b2++) {
        float S0 = lo32(T01[b2]), S1 = hi32(T01[b2]);
        float S2 = lo32(T23[b2]), S3 = hi32(T23[b2]);
        float v[7];
        v[0] = S1 + S3;                                   // qubit 0
        v[1] = S2 + S3;                                   // qubit 1
        v[2] = lo32(J0[b2]) + hi32(J0[b2]);
        v[3] = lo32(J1[b2]) + hi32(J1[b2]);
        v[4] = lo32(J2[b2]) + hi32(J2[b2]);
        v[5] = lo32(J3[b2]) + hi32(J3[b2]);
        v[6] = lo32(J4[b2]) + hi32(J4[b2]);
        sT[b2][t] = (S0 + S1) + (S2 + S3);
#pragma unroll
        for (int k = 0; k < 7; k++) {
#pragma unroll
            for (int o = 16; o > 0; o >>= 1)
                v[k] += __shfl_xor_sync(0xffffffffu, v[k], o);
        }
        if (lane == 0) {
#pragma unroll
            for (int k = 0; k < 7; k++) red[wid][b2][k] = v[k];
        }
    }
    __syncthreads();

    if (wid < BPG) {
        const int b2 = wid;
        float v[8];
#pragma unroll
        for (int k = 0; k < 8; k++) v[k] = sT[b2][lane + 32 * k];
        float tt = ((v[0] + v[1]) + (v[2] + v[3])) + ((v[4] + v[5]) + (v[6] + v[7]));
        float m[8];
        m[5] = (v[1] + v[3]) + (v[5] + v[7]);             // qubit 7
        m[6] = (v[2] + v[3]) + (v[6] + v[7]);             // qubit 8
        m[7] = (v[4] + v[5]) + (v[6] + v[7]);             // qubit 9
#pragma unroll
        for (int k = 0; k < 5; k++)
            m[k] = ((lane >> k) & 1) ? tt : 0.f;          // qubits 2..6
#pragma unroll
        for (int o = 16; o > 0; o >>= 1) {
            tt += __shfl_xor_sync(0xffffffffu, tt, o);
#pragma unroll
            for (int k = 0; k < 8; k++)
                m[k] += __shfl_xor_sync(0xffffffffu, m[k], o);
        }
        if (lane == 0) {
            float q[21];
#pragma unroll
            for (int k = 0; k < 7; k++) {
                float s = 0.f;
#pragma unroll
                for (int w = 0; w < TPB / 32; w++) s += red[w][b2][k];
                q[(k < 2) ? k : (8 + k)] = s;             // q0,q1, q10..q14
            }
#pragma unroll
            for (int k = 0; k < 8; k++) q[2 + k] = m[k];  // qubits 2..9
#pragma unroll
            for (int k = 0; k < 5; k++)
                q[15 + k] = ((chunk >> k) & 1) ? tt : 0.f;
            q[20] = tt;
            float* dst = &g_part[(size_t)blockIdx.x * (BPG * 21) + b2 * 21];
#pragma unroll
            for (int k = 0; k < 21; k++) dst[k] = q[k];
        }
    }
}

// ---------------------------------------------------------------------------
// Kernel 3: one block per batch, 672 threads, smem tree + matvec.
// ---------------------------------------------------------------------------
__global__ void __launch_bounds__(672) k_final(const float* __restrict__ Wi,
                                               const float* __restrict__ bi,
                                               float* __restrict__ out) {
    const int b  = blockIdx.x;
    const int bg = b >> 1, b2 = b & 1;
    const int t  = threadIdx.x;
    const int c  = t / 21, k = t % 21;

    __shared__ float sm[CHUNKS * 21];
    sm[t] = __ldg(&g_part[(size_t)(c * NGRP + bg) * (BPG * 21) + b2 * 21 + k]);
    __syncthreads();

#pragma unroll
    for (int step = CHUNKS / 2; step >= 1; step >>= 1) {
        if (c < step) sm[c * 21 + k] += sm[(c + step) * 21 + k];
        __syncthreads();
    }

    if (t < NQ) {
        const float inv = 1.f / sm[20];
        float acc = bi[t];
#pragma unroll
        for (int q = 0; q < NQ; q++) acc += (sm[q] * inv) * Wi[q * NQ + t];
        out[b * NQ + t] = tanhf(acc);
    }
}

// ---------------------------------------------------------------------------
// Launch: 3 graph-capturable kernels, no syncs, no allocations.
// ---------------------------------------------------------------------------
extern "C" void kernel_launch(void* const* d_in, const int* in_sizes, int n_in,
                              void* d_out, int out_size) {
    int i_amps = 7, i_noise = 8, i_Wi = 9, i_bi = 10;
    for (int i = 0; i < n_in; i++) {
        const long sz = in_sizes[i];
        if (sz == (long)BB * (long)DIM)      i_amps  = i;
        else if (sz == (long)NL * (long)DIM) i_noise = i;
        else if (sz == NQ * NQ)              i_Wi    = i;
        else if (sz == NQ)                   i_bi    = i;
    }

    const float* noise = (const float*)d_in[i_noise];
    const float* amps  = (const float*)d_in[i_amps];
    const float* Wi    = (const float*)d_in[i_Wi];
    const float* bi    = (const float*)d_in[i_bi];
    float* out         = (float*)d_out;

    k_prodG <<<NF4 / TPB1, TPB1>>>(noise);      // 512 blocks x 512 thr, 1 wave
    k_bitsum<<<CHUNKS * NGRP, TPB>>>(amps);     // 512 blocks (R15, best)
    k_final <<<BB, 672>>>(Wi, bi, out);         //  32 blocks
}